// round 9
// baseline (speedup 1.0000x reference)
#include <cuda_runtime.h>
#include <cuda_bf16.h>
#include <cstdint>

// ============================================================
// GCN GEMMs at the mma.sync roofline: bf16 hh term (f32 acc)
// + int8 cross terms (A_hi*B_lo + A_lo*B_hi) in ONE shared s32
// accumulator at 2x tensor rate. 2 MMA-equivalents instead of 3.
//   D = accF + accS * sA_i * sB_j / 256
// Per-row scales s = rowmax/127; q_hi = round(v/s),
// q_lo = round((v - bf16(v)) * 256 / s)   (|lo| <= rowmax/256).
// ============================================================

static constexpr unsigned NE = 32u * 512u * 512u;     // 8M elems
static constexpr unsigned NW = 512u * 512u;
static constexpr unsigned RROWS = 32u * 512u;         // rows of batched tensors

// fp32 scratch for intermediates (S^T / H alternate through it)
static __device__ float g_Ff[NE];
static __device__ float g_Wtf[NW];                    // transposed weight scratch

// quantized operand sets: hi bf16, hi s8, lo s8, per-row scale
static __device__ __nv_bfloat16 g_Xhi[NE];  static __device__ char g_X8h[NE], g_X8l[NE];  static __device__ float g_Xsc[RROWS];
static __device__ __nv_bfloat16 g_Jhi[NE];  static __device__ char g_J8h[NE], g_J8l[NE];  static __device__ float g_Jsc[RROWS];
static __device__ __nv_bfloat16 g_Shi[NE];  static __device__ char g_S8h[NE], g_S8l[NE];  static __device__ float g_Ssc[RROWS];
static __device__ __nv_bfloat16 g_Hhi[NE];  static __device__ char g_H8h[NE], g_H8l[NE];  static __device__ float g_Hsc[RROWS];
static __device__ __nv_bfloat16 g_Whi[3*NW]; static __device__ char g_W8h[3*NW], g_W8l[3*NW]; static __device__ float g_Wsc[3*512];

__device__ __forceinline__ uint32_t smem_u32(const void* p) {
    uint32_t a;
    asm("{ .reg .u64 t; cvta.to.shared.u64 t, %1; cvt.u32.u64 %0, t; }"
        : "=r"(a) : "l"(p));
    return a;
}

#define LDSM_X4(r0, r1, r2, r3, addr) \
    asm volatile("ldmatrix.sync.aligned.m8n8.x4.shared.b16 {%0,%1,%2,%3}, [%4];" \
                 : "=r"(r0), "=r"(r1), "=r"(r2), "=r"(r3) : "r"(addr))

#define CP_ASYNC16(dst, src) \
    asm volatile("cp.async.cg.shared.global [%0], [%1], 16;" \
                 :: "r"(dst), "l"(src) : "memory")
#define CP_COMMIT() asm volatile("cp.async.commit_group;" ::: "memory")
#define CP_WAIT(n)  asm volatile("cp.async.wait_group %0;" :: "n"(n) : "memory")

__device__ __forceinline__ void mma16816(float* d, const uint32_t* a,
                                         uint32_t b0, uint32_t b1) {
    asm volatile(
        "mma.sync.aligned.m16n8k16.row.col.f32.bf16.bf16.f32 "
        "{%0,%1,%2,%3}, {%4,%5,%6,%7}, {%8,%9}, {%0,%1,%2,%3};"
        : "+f"(d[0]), "+f"(d[1]), "+f"(d[2]), "+f"(d[3])
        : "r"(a[0]), "r"(a[1]), "r"(a[2]), "r"(a[3]), "r"(b0), "r"(b1));
}

__device__ __forceinline__ void imma16832(int* d, const uint32_t* a,
                                          uint32_t b0, uint32_t b1) {
    asm volatile(
        "mma.sync.aligned.m16n8k32.row.col.s32.s8.s8.s32 "
        "{%0,%1,%2,%3}, {%4,%5,%6,%7}, {%8,%9}, {%0,%1,%2,%3};"
        : "+r"(d[0]), "+r"(d[1]), "+r"(d[2]), "+r"(d[3])
        : "r"(a[0]), "r"(a[1]), "r"(a[2]), "r"(a[3]), "r"(b0), "r"(b1));
}

// SMEM layout per stage (32KB):
//  bf16 tiles 128x32 (64B rows, XOR-swizzled 16B chunks q0..3)
//  s8   tiles 128x32 (32B rows, XOR-swizzled 16B chunks q0..1)
static constexpr int T16 = 128 * 64;     // 8KB
static constexpr int T8  = 128 * 32;     // 4KB
static constexpr int OFF_AH16 = 0;
static constexpr int OFF_BH16 = T16;
static constexpr int OFF_A8H  = 2 * T16;
static constexpr int OFF_A8L  = 2 * T16 + T8;
static constexpr int OFF_B8H  = 2 * T16 + 2 * T8;
static constexpr int OFF_B8L  = 2 * T16 + 3 * T8;
static constexpr int STAGE = 2 * T16 + 4 * T8;       // 32KB
static constexpr int NSTG  = 3;
static constexpr int SMEM_BYTES = NSTG * STAGE;      // 96KB

__device__ __forceinline__ uint32_t sw16(int row, int q) {
    return (uint32_t)row * 64u + (uint32_t)((q ^ ((row >> 1) & 3)) << 4);
}
__device__ __forceinline__ uint32_t sw8(int row, int q) {
    return (uint32_t)row * 32u + (uint32_t)((q ^ ((row >> 2) & 1)) << 4);
}

// EPI: 0 = plain fp32, 1 = bias+relu fp32, 2 = bias fp32
template <int EPI>
__global__ __launch_bounds__(256, 1)
void hgemm(const __nv_bfloat16* __restrict__ Ahi, const char* __restrict__ A8h,
           const char* __restrict__ A8l, const float* __restrict__ scA,
           const __nv_bfloat16* __restrict__ Bhi, const char* __restrict__ B8h,
           const char* __restrict__ B8l, const float* __restrict__ scB,
           const float* __restrict__ bias, float* __restrict__ Call,
           long strideA, long strideB)
{
    extern __shared__ char smem[];
    const uint32_t sb = smem_u32(smem);
    const int tid  = threadIdx.x;
    const int wid  = tid >> 5;
    const int lane = tid & 31;

    const long s = 512l * 512l;
    const size_t offA = (size_t)blockIdx.z * strideA;
    const size_t offB = (size_t)blockIdx.z * strideB;

    const int rowBlock = blockIdx.y * 128;
    const int colBlock = blockIdx.x * 128;

    const int wm = (wid >> 2) * 64;    // 2 warps in M
    const int wn = (wid & 3) * 32;     // 4 warps in N

    // ---- cp.async geometry ----
    // bf16: 2 chunks per tile per thread
    const int cQ = tid & 3;
    uint32_t d16[2];
    size_t gA16[2], gB16[2];
    #pragma unroll
    for (int i = 0; i < 2; ++i) {
        const int row = (tid >> 2) + i * 64;
        d16[i] = sw16(row, cQ);
        gA16[i] = offA + (size_t)(rowBlock + row) * 512 + cQ * 8;
        gB16[i] = offB + (size_t)(colBlock + row) * 512 + cQ * 8;
    }
    // s8: 1 chunk per tile per thread
    const int r8 = tid >> 1;
    const int q8 = tid & 1;
    const uint32_t d8 = sw8(r8, q8);
    const size_t gA8 = offA + (size_t)(rowBlock + r8) * 512 + q8 * 16;
    const size_t gB8 = offB + (size_t)(colBlock + r8) * 512 + q8 * 16;

    auto issue = [&](int c) {
        const uint32_t st = sb + (uint32_t)(c % NSTG) * STAGE;
        const int k0 = c * 32;
        #pragma unroll
        for (int i = 0; i < 2; ++i) {
            CP_ASYNC16(st + OFF_AH16 + d16[i], Ahi + gA16[i] + k0);
            CP_ASYNC16(st + OFF_BH16 + d16[i], Bhi + gB16[i] + k0);
        }
        CP_ASYNC16(st + OFF_A8H + d8, A8h + gA8 + k0);
        CP_ASYNC16(st + OFF_A8L + d8, A8l + gA8 + k0);
        CP_ASYNC16(st + OFF_B8H + d8, B8h + gB8 + k0);
        CP_ASYNC16(st + OFF_B8L + d8, B8l + gB8 + k0);
        CP_COMMIT();
    };

    // ---- ldmatrix geometry ----
    const int lmRow = lane & 15;
    const int lmQ   = lane >> 4;       // bf16: chunk sel, s8: chunk sel
    uint32_t aR16[4], bR16[2];
    int aX16[4], bX16[2];
    uint32_t a8off[4], b8off[2];
    #pragma unroll
    for (int ti = 0; ti < 4; ++ti) {
        const int r = wm + ti * 16 + lmRow;
        aR16[ti] = (uint32_t)r * 64u;
        aX16[ti] = (r >> 1) & 3;
        a8off[ti] = (uint32_t)r * 32u + (uint32_t)((lmQ ^ ((r >> 2) & 1)) << 4);
    }
    #pragma unroll
    for (int g = 0; g < 2; ++g) {
        const int r = wn + g * 16 + lmRow;
        bR16[g] = (uint32_t)r * 64u;
        bX16[g] = (r >> 1) & 3;
        b8off[g] = (uint32_t)r * 32u + (uint32_t)((lmQ ^ ((r >> 2) & 1)) << 4);
    }

    float accF[4][4][4] = {};
    int   accS[4][4][4] = {};

    issue(0);
    issue(1);

    for (int c = 0; c < 16; ++c) {
        if (c == 15) { CP_WAIT(0); } else { CP_WAIT(1); }
        __syncthreads();
        if (c + 2 < 16) issue(c + 2);

        const uint32_t st = sb + (uint32_t)(c % NSTG) * STAGE;

        // ---- bf16 hh: 2 x k16 ----
        #pragma unroll
        for (int kk = 0; kk < 2; ++kk) {
            const int q = lmQ + kk * 2;
            uint32_t af[4][4], bb[2][4];
            #pragma unroll
            for (int g = 0; g < 2; ++g) {
                const uint32_t sw = (uint32_t)((q ^ bX16[g]) << 4);
                LDSM_X4(bb[g][0], bb[g][1], bb[g][2], bb[g][3],
                        st + OFF_BH16 + bR16[g] + sw);
            }
            #pragma unroll
            for (int ti = 0; ti < 4; ++ti) {
                const uint32_t sw = (uint32_t)((q ^ aX16[ti]) << 4);
                LDSM_X4(af[ti][0], af[ti][1], af[ti][2], af[ti][3],
                        st + OFF_AH16 + aR16[ti] + sw);
            }
            #pragma unroll
            for (int ti = 0; ti < 4; ++ti)
                #pragma unroll
                for (int tj = 0; tj < 4; ++tj)
                    mma16816(accF[ti][tj], af[ti],
                             bb[tj >> 1][tj & 1], bb[tj >> 1][2 + (tj & 1)]);
        }

        // ---- int8 cross: k32 ----
        {
            uint32_t a8[4][4], b8[2][4];
            // A_hi(s8) x B_lo(s8)
            #pragma unroll
            for (int g = 0; g < 2; ++g)
                LDSM_X4(b8[g][0], b8[g][1], b8[g][2], b8[g][3],
                        st + OFF_B8L + b8off[g]);
            #pragma unroll
            for (int ti = 0; ti < 4; ++ti)
                LDSM_X4(a8[ti][0], a8[ti][1], a8[ti][2], a8[ti][3],
                        st + OFF_A8H + a8off[ti]);
            #pragma unroll
            for (int ti = 0; ti < 4; ++ti)
                #pragma unroll
                for (int tj = 0; tj < 4; ++tj)
                    imma16832(accS[ti][tj], a8[ti],
                              b8[tj >> 1][tj & 1], b8[tj >> 1][2 + (tj & 1)]);
            // A_lo(s8) x B_hi(s8)
            #pragma unroll
            for (int ti = 0; ti < 4; ++ti)
                LDSM_X4(a8[ti][0], a8[ti][1], a8[ti][2], a8[ti][3],
                        st + OFF_A8L + a8off[ti]);
            #pragma unroll
            for (int g = 0; g < 2; ++g)
                LDSM_X4(b8[g][0], b8[g][1], b8[g][2], b8[g][3],
                        st + OFF_B8H + b8off[g]);
            #pragma unroll
            for (int ti = 0; ti < 4; ++ti)
                #pragma unroll
                for (int tj = 0; tj < 4; ++tj)
                    imma16832(accS[ti][tj], a8[ti],
                              b8[tj >> 1][tj & 1], b8[tj >> 1][2 + (tj & 1)]);
        }
    }

    // ---- epilogue: combine, dequant cross, store fp32 ----
    const size_t offC = (size_t)blockIdx.z * s;
    const float* scAp = scA + (strideA ? (size_t)blockIdx.z * 512 : 0);
    const float* scBp = scB + (strideB ? (size_t)blockIdx.z * 512 : 0);

    #pragma unroll
    for (int ti = 0; ti < 4; ++ti) {
        const int m0 = rowBlock + wm + ti * 16 + (lane >> 2);
        const float sA0 = __ldg(scAp + m0) * (1.0f / 256.0f);
        const float sA1 = __ldg(scAp + m0 + 8) * (1.0f / 256.0f);
        #pragma unroll
        for (int tj = 0; tj < 4; ++tj) {
            const int n0 = colBlock + wn + tj * 8 + (lane & 3) * 2;
            const float sB0 = __ldg(scBp + n0);
            const float sB1 = __ldg(scBp + n0 + 1);
            float2 v0, v1;
            v0.x = fmaf((float)accS[ti][tj][0], sA0 * sB0, accF[ti][tj][0]);
            v0.y = fmaf((float)accS[ti][tj][1], sA0 * sB1, accF[ti][tj][1]);
            v1.x = fmaf((float)accS[ti][tj][2], sA1 * sB0, accF[ti][tj][2]);
            v1.y = fmaf((float)accS[ti][tj][3], sA1 * sB1, accF[ti][tj][3]);
            if (EPI != 0) {
                const float bx = __ldg(bias + n0), by = __ldg(bias + n0 + 1);
                v0.x += bx; v0.y += by; v1.x += bx; v1.y += by;
                if (EPI == 1) {
                    v0.x = fmaxf(v0.x, 0.f); v0.y = fmaxf(v0.y, 0.f);
                    v1.x = fmaxf(v1.x, 0.f); v1.y = fmaxf(v1.y, 0.f);
                }
            }
            const size_t p0 = offC + (size_t)m0 * 512 + n0;
            *(float2*)(Call + p0) = v0;
            *(float2*)(Call + p0 + 8 * 512) = v1;
        }
    }
}

// per-row quantize: fp32 row -> bf16 hi + s8 hi + s8 lo + scale
__global__ __launch_bounds__(128)
void quant_rows(const float* __restrict__ in,
                __nv_bfloat16* __restrict__ hi,
                char* __restrict__ q8h, char* __restrict__ q8l,
                float* __restrict__ sc)
{
    const int row = blockIdx.x;
    const int tid = threadIdx.x;
    const float4 v = ((const float4*)(in + (size_t)row * 512))[tid];

    float m = fmaxf(fmaxf(fabsf(v.x), fabsf(v.y)), fmaxf(fabsf(v.z), fabsf(v.w)));
    #pragma unroll
    for (int o = 16; o; o >>= 1) m = fmaxf(m, __shfl_xor_sync(0xFFFFFFFFu, m, o));
    __shared__ float wm_[4];
    if ((tid & 31) == 0) wm_[tid >> 5] = m;
    __syncthreads();
    m = fmaxf(fmaxf(wm_[0], wm_[1]), fmaxf(wm_[2], wm_[3]));

    float scale, inv;
    if (m > 0.f) { scale = m * (1.0f / 127.0f); inv = 127.0f / m; }
    else         { scale = 1.0f; inv = 0.0f; }
    if (tid == 0) sc[row] = scale;

    float e[4] = {v.x, v.y, v.z, v.w};
    __nv_bfloat16 h[4];
    char qh[4], ql[4];
    #pragma unroll
    for (int i = 0; i < 4; ++i) {
        h[i] = __float2bfloat16_rn(e[i]);
        const float lo = e[i] - __bfloat162float(h[i]);
        float a = rintf(e[i] * inv);
        float b = rintf(lo * inv * 256.0f);
        a = fminf(fmaxf(a, -127.f), 127.f);
        b = fminf(fmaxf(b, -127.f), 127.f);
        qh[i] = (char)(int)a;
        ql[i] = (char)(int)b;
    }
    __nv_bfloat162 h01, h23;
    h01.x = h[0]; h01.y = h[1]; h23.x = h[2]; h23.y = h[3];
    uint2 hw = make_uint2(*(uint32_t*)&h01, *(uint32_t*)&h23);
    ((uint2*)hi)[(size_t)row * 128 + tid] = hw;
    ((uint32_t*)q8h)[(size_t)row * 128 + tid] = *(uint32_t*)qh;
    ((uint32_t*)q8l)[(size_t)row * 128 + tid] = *(uint32_t*)ql;
}

// 512x512 fp32 transpose (weights)
__global__ void transpose512(const float* __restrict__ in, float* __restrict__ out)
{
    __shared__ float t[32][33];
    const int bx = blockIdx.x * 32, by = blockIdx.y * 32;
    const int x = threadIdx.x, y = threadIdx.y;   // 32x8
    #pragma unroll
    for (int j = 0; j < 32; j += 8)
        t[y + j][x] = in[(size_t)(by + y + j) * 512 + bx + x];
    __syncthreads();
    #pragma unroll
    for (int j = 0; j < 32; j += 8)
        out[(size_t)(bx + y + j) * 512 + by + x] = t[x][y + j];
}

extern "C" void kernel_launch(void* const* d_in, const int* in_sizes, int n_in,
                              void* d_out, int out_size)
{
    const float* X   = (const float*)d_in[0];
    const float* adj = (const float*)d_in[1];
    const float* W0  = (const float*)d_in[2];
    const float* b0  = (const float*)d_in[3];
    const float* W1  = (const float*)d_in[4];
    const float* b1  = (const float*)d_in[5];
    const float* W2  = (const float*)d_in[6];
    const float* b2  = (const float*)d_in[7];
    float* out = (float*)d_out;

    float *Ff, *Wtf;
    cudaGetSymbolAddress((void**)&Ff,  g_Ff);
    cudaGetSymbolAddress((void**)&Wtf, g_Wtf);
    __nv_bfloat16 *Xhi, *Jhi, *Shi, *Hhi, *Whi;
    char *X8h,*X8l,*J8h,*J8l,*S8h,*S8l,*H8h,*H8l,*W8h,*W8l;
    float *Xsc,*Jsc,*Ssc,*Hsc,*Wsc;
    cudaGetSymbolAddress((void**)&Xhi, g_Xhi); cudaGetSymbolAddress((void**)&X8h, g_X8h);
    cudaGetSymbolAddress((void**)&X8l, g_X8l); cudaGetSymbolAddress((void**)&Xsc, g_Xsc);
    cudaGetSymbolAddress((void**)&Jhi, g_Jhi); cudaGetSymbolAddress((void**)&J8h, g_J8h);
    cudaGetSymbolAddress((void**)&J8l, g_J8l); cudaGetSymbolAddress((void**)&Jsc, g_Jsc);
    cudaGetSymbolAddress((void**)&Shi, g_Shi); cudaGetSymbolAddress((void**)&S8h, g_S8h);
    cudaGetSymbolAddress((void**)&S8l, g_S8l); cudaGetSymbolAddress((void**)&Ssc, g_Ssc);
    cudaGetSymbolAddress((void**)&Hhi, g_Hhi); cudaGetSymbolAddress((void**)&H8h, g_H8h);
    cudaGetSymbolAddress((void**)&H8l, g_H8l); cudaGetSymbolAddress((void**)&Hsc, g_Hsc);
    cudaGetSymbolAddress((void**)&Whi, g_Whi); cudaGetSymbolAddress((void**)&W8h, g_W8h);
    cudaGetSymbolAddress((void**)&W8l, g_W8l); cudaGetSymbolAddress((void**)&Wsc, g_Wsc);

    cudaFuncSetAttribute(hgemm<0>, cudaFuncAttributeMaxDynamicSharedMemorySize, SMEM_BYTES);
    cudaFuncSetAttribute(hgemm<1>, cudaFuncAttributeMaxDynamicSharedMemorySize, SMEM_BYTES);
    cudaFuncSetAttribute(hgemm<2>, cudaFuncAttributeMaxDynamicSharedMemorySize, SMEM_BYTES);

    const long s = 512l * 512l;
    const dim3 tgrid(16, 16), tblk(32, 8);

    // quantize inputs
    quant_rows<<<RROWS, 128>>>(X,   Xhi, X8h, X8l, Xsc);
    quant_rows<<<RROWS, 128>>>(adj, Jhi, J8h, J8l, Jsc);
    const float* Ws[3] = {W0, W1, W2};
    for (int w = 0; w < 3; ++w) {
        transpose512<<<tgrid, tblk>>>(Ws[w], Wtf);
        quant_rows<<<512, 128>>>(Wtf, Whi + (size_t)w * s,
                                 W8h + (size_t)w * s, W8l + (size_t)w * s,
                                 Wsc + (size_t)w * 512);
    }

    const dim3 grid(4, 4, 32), blk(256);

    // Layer 0:  S^T = (X @ W0)^T  via  A=Wt0, B=X
    hgemm<0><<<grid, blk, SMEM_BYTES>>>(Whi, W8h, W8l, Wsc,
                                        Xhi, X8h, X8l, Xsc,
                                        nullptr, Ff, 0, s);
    quant_rows<<<RROWS, 128>>>(Ff, Shi, S8h, S8l, Ssc);
    hgemm<1><<<grid, blk, SMEM_BYTES>>>(Jhi, J8h, J8l, Jsc,
                                        Shi, S8h, S8l, Ssc,
                                        b0, Ff, s, s);
    quant_rows<<<RROWS, 128>>>(Ff, Hhi, H8h, H8l, Hsc);
    // Layer 1
    hgemm<0><<<grid, blk, SMEM_BYTES>>>(Whi + s, W8h + s, W8l + s, Wsc + 512,
                                        Hhi, H8h, H8l, Hsc,
                                        nullptr, Ff, 0, s);
    quant_rows<<<RROWS, 128>>>(Ff, Shi, S8h, S8l, Ssc);
    hgemm<1><<<grid, blk, SMEM_BYTES>>>(Jhi, J8h, J8l, Jsc,
                                        Shi, S8h, S8l, Ssc,
                                        b1, Ff, s, s);
    quant_rows<<<RROWS, 128>>>(Ff, Hhi, H8h, H8l, Hsc);
    // Layer 2 (no relu)
    hgemm<0><<<grid, blk, SMEM_BYTES>>>(Whi + 2*s, W8h + 2*s, W8l + 2*s, Wsc + 1024,
                                        Hhi, H8h, H8l, Hsc,
                                        nullptr, Ff, 0, s);
    quant_rows<<<RROWS, 128>>>(Ff, Shi, S8h, S8l, Ssc);
    hgemm<2><<<grid, blk, SMEM_BYTES>>>(Jhi, J8h, J8l, Jsc,
                                        Shi, S8h, S8l, Ssc,
                                        b2, out, s, s);
}

// round 10
// speedup vs baseline: 2.2734x; 2.2734x over previous
#include <cuda_runtime.h>
#include <cuda_bf16.h>
#include <cstdint>

// ============================================================
// GCN GEMMs: heterogeneous tensor + SIMT split.
//   graphs [0, ZT): bf16 hi/lo 3-term mma.sync path (R7, at HMMA floor)
//   graphs [ZT,32): exact fp32 SIMT FFMA path (idle FMA pipe)
// Both run in ONE launch (branch on blockIdx.z) so the pipes overlap.
// All epilogues emit fp32 + bf16 hi/lo so both paths interoperate.
// ============================================================

static constexpr unsigned NE = 32u * 512u * 512u;
static constexpr unsigned NW = 512u * 512u;
static constexpr int ZT = 27;                     // graphs on tensor path

static __device__ __nv_bfloat16 g_Xhi[NE],  g_Xlo[NE];
static __device__ __nv_bfloat16 g_Jhi[NE],  g_Jlo[NE];
static __device__ __nv_bfloat16 g_Shi[NE],  g_Slo[NE];
static __device__ __nv_bfloat16 g_Hhi[NE],  g_Hlo[NE];
static __device__ __nv_bfloat16 g_Wthi[3*NW], g_Wtlo[3*NW];
static __device__ float g_Sf[NE], g_Hf[NE];       // fp32 mirrors
static __device__ float g_Wtf[3*NW];              // fp32 transposed weights

__device__ __forceinline__ uint32_t smem_u32(const void* p) {
    uint32_t a;
    asm("{ .reg .u64 t; cvta.to.shared.u64 t, %1; cvt.u32.u64 %0, t; }"
        : "=r"(a) : "l"(p));
    return a;
}

#define LDSM_X4(r0, r1, r2, r3, addr) \
    asm volatile("ldmatrix.sync.aligned.m8n8.x4.shared.b16 {%0,%1,%2,%3}, [%4];" \
                 : "=r"(r0), "=r"(r1), "=r"(r2), "=r"(r3) : "r"(addr))

#define CP_ASYNC16(dst, src) \
    asm volatile("cp.async.cg.shared.global [%0], [%1], 16;" \
                 :: "r"(dst), "l"(src) : "memory")
#define CP_COMMIT() asm volatile("cp.async.commit_group;" ::: "memory")
#define CP_WAIT(n)  asm volatile("cp.async.wait_group %0;" :: "n"(n) : "memory")

__device__ __forceinline__ void mma16816(float* d, const uint32_t* a,
                                         uint32_t b0, uint32_t b1) {
    asm volatile(
        "mma.sync.aligned.m16n8k16.row.col.f32.bf16.bf16.f32 "
        "{%0,%1,%2,%3}, {%4,%5,%6,%7}, {%8,%9}, {%0,%1,%2,%3};"
        : "+f"(d[0]), "+f"(d[1]), "+f"(d[2]), "+f"(d[3])
        : "r"(a[0]), "r"(a[1]), "r"(a[2]), "r"(a[3]), "r"(b0), "r"(b1));
}

static constexpr int TILE  = 128 * 64;           // 8KB bf16 tile
static constexpr int OFF_AH = 0, OFF_AL = TILE, OFF_BH = 2*TILE, OFF_BL = 3*TILE;
static constexpr int STAGE = 4 * TILE;           // 32KB
static constexpr int NSTG  = 3;
static constexpr int SMEM_BYTES = NSTG * STAGE;  // 96KB

__device__ __forceinline__ uint32_t sw_off(int row, int q) {
    return (uint32_t)row * 64u + (uint32_t)((q ^ ((row >> 1) & 3)) << 4);
}

__device__ __forceinline__ void split_store(float2 v, __nv_bfloat16* Chi,
                                            __nv_bfloat16* Clo, size_t p) {
    __nv_bfloat162 h = __floats2bfloat162_rn(v.x, v.y);
    __nv_bfloat162 l = __floats2bfloat162_rn(v.x - __bfloat162float(h.x),
                                             v.y - __bfloat162float(h.y));
    *(uint32_t*)(Chi + p) = *(uint32_t*)&h;
    *(uint32_t*)(Clo + p) = *(uint32_t*)&l;
}

// ---------------- SIMT fp32 path: 128x64 tile, 256 threads ----------------
// As: [16][132] floats, Bs: [16][68] floats inside dynamic smem.
template <int EPI>
__device__ void simt_gemm(const float* __restrict__ Af, const float* __restrict__ Bf,
                          const float* __restrict__ bias,
                          float* __restrict__ Cf,
                          __nv_bfloat16* __restrict__ Chi, __nv_bfloat16* __restrict__ Clo,
                          size_t offA, size_t offB, size_t offC,
                          int rowBlock, int colBlock, char* smem)
{
    float* As = (float*)smem;              // 16 x 132
    float* Bs = As + 16 * 132;             // 16 x 68
    const int tid = threadIdx.x;
    const int tx = tid & 7;                // 8 col-threads (x8 cols)
    const int ty = tid >> 3;               // 32 row-threads (x4 rows)
    const int aRow = tid >> 2;             // 0..63
    const int k4   = tid & 3;

    float acc[4][8] = {};

    for (int k0 = 0; k0 < 512; k0 += 16) {
        #pragma unroll
        for (int r = 0; r < 2; ++r) {
            const int row = aRow + r * 64;
            const float4 v = *(const float4*)(Af + offA
                               + (size_t)(rowBlock + row) * 512 + k0 + k4 * 4);
            As[(k4 * 4 + 0) * 132 + row] = v.x;
            As[(k4 * 4 + 1) * 132 + row] = v.y;
            As[(k4 * 4 + 2) * 132 + row] = v.z;
            As[(k4 * 4 + 3) * 132 + row] = v.w;
        }
        {
            const float4 v = *(const float4*)(Bf + offB
                               + (size_t)(colBlock + aRow) * 512 + k0 + k4 * 4);
            Bs[(k4 * 4 + 0) * 68 + aRow] = v.x;
            Bs[(k4 * 4 + 1) * 68 + aRow] = v.y;
            Bs[(k4 * 4 + 2) * 68 + aRow] = v.z;
            Bs[(k4 * 4 + 3) * 68 + aRow] = v.w;
        }
        __syncthreads();
        #pragma unroll
        for (int kk = 0; kk < 16; ++kk) {
            float ra[4], rb[8];
            #pragma unroll
            for (int i = 0; i < 4; ++i) ra[i] = As[kk * 132 + ty * 4 + i];
            #pragma unroll
            for (int j = 0; j < 8; ++j) rb[j] = Bs[kk * 68 + tx * 8 + j];
            #pragma unroll
            for (int i = 0; i < 4; ++i)
                #pragma unroll
                for (int j = 0; j < 8; ++j)
                    acc[i][j] += ra[i] * rb[j];
        }
        __syncthreads();
    }

    #pragma unroll
    for (int i = 0; i < 4; ++i) {
        const int m = rowBlock + ty * 4 + i;
        #pragma unroll
        for (int j0 = 0; j0 < 8; j0 += 4) {
            const int n = colBlock + tx * 8 + j0;
            float4 v = make_float4(acc[i][j0], acc[i][j0+1], acc[i][j0+2], acc[i][j0+3]);
            if (EPI != 0) {
                v.x += __ldg(bias + n + 0); v.y += __ldg(bias + n + 1);
                v.z += __ldg(bias + n + 2); v.w += __ldg(bias + n + 3);
                if (EPI == 1) {
                    v.x = fmaxf(v.x, 0.f); v.y = fmaxf(v.y, 0.f);
                    v.z = fmaxf(v.z, 0.f); v.w = fmaxf(v.w, 0.f);
                }
            }
            const size_t p = offC + (size_t)m * 512 + n;
            *(float4*)(Cf + p) = v;
            if (EPI != 2) {
                split_store(make_float2(v.x, v.y), Chi, Clo, p);
                split_store(make_float2(v.z, v.w), Chi, Clo, p + 2);
            }
        }
    }
}

// EPI: 0 = plain, 1 = bias+relu, 2 = bias (final, fp32 only)
template <int EPI>
__global__ __launch_bounds__(256, 2)
void hgemm(const __nv_bfloat16* __restrict__ Ahi, const __nv_bfloat16* __restrict__ Alo,
           const float* __restrict__ Af,
           const __nv_bfloat16* __restrict__ Bhi, const __nv_bfloat16* __restrict__ Blo,
           const float* __restrict__ Bf,
           const float* __restrict__ bias,
           float* __restrict__ Cf,
           __nv_bfloat16* __restrict__ Chi, __nv_bfloat16* __restrict__ Clo,
           long strideA, long strideB)
{
    extern __shared__ char smem[];
    const long s = 512l * 512l;
    const int z = blockIdx.z;
    const size_t offA = (size_t)z * strideA;
    const size_t offB = (size_t)z * strideB;
    const size_t offC = (size_t)z * s;

    if (z >= ZT) {
        // SIMT fp32 path: 128x64 tiles, grid x in [0,8)
        simt_gemm<EPI>(Af, Bf, bias, Cf, Chi, Clo, offA, offB, offC,
                       blockIdx.y * 128, blockIdx.x * 64, smem);
        return;
    }
    if (blockIdx.x >= 4) return;   // tensor path uses 4x4 tiles only

    const uint32_t sb = smem_u32(smem);
    const int tid  = threadIdx.x;
    const int wid  = tid >> 5;
    const int lane = tid & 31;

    const int rowBlock = blockIdx.y * 128;
    const int colBlock = blockIdx.x * 128;

    const int wm = (wid >> 2) * 64;
    const int wn = (wid & 3) * 32;

    const int cQ = tid & 3;
    uint32_t dOf[2];
    size_t gA[2], gB[2];
    #pragma unroll
    for (int i = 0; i < 2; ++i) {
        const int row = (tid >> 2) + i * 64;
        dOf[i] = sw_off(row, cQ);
        gA[i] = offA + (size_t)(rowBlock + row) * 512 + cQ * 8;
        gB[i] = offB + (size_t)(colBlock + row) * 512 + cQ * 8;
    }

    auto issue = [&](int c) {
        const uint32_t st = sb + (uint32_t)(c % NSTG) * STAGE;
        const int k0 = c * 32;
        #pragma unroll
        for (int i = 0; i < 2; ++i) {
            CP_ASYNC16(st + OFF_AH + dOf[i], Ahi + gA[i] + k0);
            CP_ASYNC16(st + OFF_AL + dOf[i], Alo + gA[i] + k0);
            CP_ASYNC16(st + OFF_BH + dOf[i], Bhi + gB[i] + k0);
            CP_ASYNC16(st + OFF_BL + dOf[i], Blo + gB[i] + k0);
        }
        CP_COMMIT();
    };

    const int lmRow = lane & 15;
    const int lmQ   = lane >> 4;
    uint32_t aRow[4], bRow[2];
    int aXr[4], bXr[2];
    #pragma unroll
    for (int ti = 0; ti < 4; ++ti) {
        const int r = wm + ti * 16 + lmRow;
        aRow[ti] = (uint32_t)r * 64u;
        aXr[ti]  = (r >> 1) & 3;
    }
    #pragma unroll
    for (int g = 0; g < 2; ++g) {
        const int r = wn + g * 16 + lmRow;
        bRow[g] = (uint32_t)r * 64u;
        bXr[g]  = (r >> 1) & 3;
    }

    float acc[4][4][4] = {};

    issue(0);
    issue(1);

    for (int c = 0; c < 16; ++c) {
        if (c == 15) { CP_WAIT(0); } else { CP_WAIT(1); }
        __syncthreads();
        if (c + 2 < 16) issue(c + 2);

        const uint32_t st = sb + (uint32_t)(c % NSTG) * STAGE;

        #pragma unroll
        for (int kk = 0; kk < 2; ++kk) {
            const int q = lmQ + kk * 2;
            uint32_t af[4][4], al[4][4], bb[2][4];
            #pragma unroll
            for (int g = 0; g < 2; ++g) {
                const uint32_t sw = (uint32_t)((q ^ bXr[g]) << 4);
                LDSM_X4(bb[g][0], bb[g][1], bb[g][2], bb[g][3],
                        st + OFF_BH + bRow[g] + sw);
            }
            #pragma unroll
            for (int ti = 0; ti < 4; ++ti) {
                const uint32_t sw = (uint32_t)((q ^ aXr[ti]) << 4);
                LDSM_X4(af[ti][0], af[ti][1], af[ti][2], af[ti][3],
                        st + OFF_AH + aRow[ti] + sw);
            }
            #pragma unroll
            for (int ti = 0; ti < 4; ++ti)
                #pragma unroll
                for (int tj = 0; tj < 4; ++tj)
                    mma16816(acc[ti][tj], af[ti],
                             bb[tj >> 1][tj & 1], bb[tj >> 1][2 + (tj & 1)]);
            #pragma unroll
            for (int ti = 0; ti < 4; ++ti) {
                const uint32_t sw = (uint32_t)((q ^ aXr[ti]) << 4);
                LDSM_X4(al[ti][0], al[ti][1], al[ti][2], al[ti][3],
                        st + OFF_AL + aRow[ti] + sw);
            }
            #pragma unroll
            for (int ti = 0; ti < 4; ++ti)
                #pragma unroll
                for (int tj = 0; tj < 4; ++tj)
                    mma16816(acc[ti][tj], al[ti],
                             bb[tj >> 1][tj & 1], bb[tj >> 1][2 + (tj & 1)]);
            #pragma unroll
            for (int g = 0; g < 2; ++g) {
                const uint32_t sw = (uint32_t)((q ^ bXr[g]) << 4);
                LDSM_X4(bb[g][0], bb[g][1], bb[g][2], bb[g][3],
                        st + OFF_BL + bRow[g] + sw);
            }
            #pragma unroll
            for (int ti = 0; ti < 4; ++ti)
                #pragma unroll
                for (int tj = 0; tj < 4; ++tj)
                    mma16816(acc[ti][tj], af[ti],
                             bb[tj >> 1][tj & 1], bb[tj >> 1][2 + (tj & 1)]);
        }
    }

    #pragma unroll
    for (int ti = 0; ti < 4; ++ti) {
        const int m0 = rowBlock + wm + ti * 16 + (lane >> 2);
        #pragma unroll
        for (int tj = 0; tj < 4; ++tj) {
            const int n0 = colBlock + wn + tj * 8 + (lane & 3) * 2;
            float2 v0 = make_float2(acc[ti][tj][0], acc[ti][tj][1]);
            float2 v1 = make_float2(acc[ti][tj][2], acc[ti][tj][3]);
            if (EPI != 0) {
                const float bx = __ldg(bias + n0), by = __ldg(bias + n0 + 1);
                v0.x += bx; v0.y += by; v1.x += bx; v1.y += by;
                if (EPI == 1) {
                    v0.x = fmaxf(v0.x, 0.f); v0.y = fmaxf(v0.y, 0.f);
                    v1.x = fmaxf(v1.x, 0.f); v1.y = fmaxf(v1.y, 0.f);
                }
            }
            const size_t p0 = offC + (size_t)m0 * 512 + n0;
            const size_t p1 = p0 + 8 * 512;
            *(float2*)(Cf + p0) = v0;
            *(float2*)(Cf + p1) = v1;
            if (EPI != 2) {
                split_store(v0, Chi, Clo, p0);
                split_store(v1, Chi, Clo, p1);
            }
        }
    }
}

// split fp32 -> bf16 hi/lo
__global__ __launch_bounds__(256)
void split_f32(const float* __restrict__ in,
               __nv_bfloat16* __restrict__ hi, __nv_bfloat16* __restrict__ lo,
               int n4)
{
    const int i = blockIdx.x * blockDim.x + threadIdx.x;
    if (i >= n4) return;
    float4 v = ((const float4*)in)[i];
    __nv_bfloat162 h0 = __floats2bfloat162_rn(v.x, v.y);
    __nv_bfloat162 h1 = __floats2bfloat162_rn(v.z, v.w);
    __nv_bfloat162 l0 = __floats2bfloat162_rn(v.x - __bfloat162float(h0.x),
                                              v.y - __bfloat162float(h0.y));
    __nv_bfloat162 l1 = __floats2bfloat162_rn(v.z - __bfloat162float(h1.x),
                                              v.w - __bfloat162float(h1.y));
    ((uint2*)hi)[i] = make_uint2(*(uint32_t*)&h0, *(uint32_t*)&h1);
    ((uint2*)lo)[i] = make_uint2(*(uint32_t*)&l0, *(uint32_t*)&l1);
}

// transpose 512x512 fp32 -> fp32 + bf16 hi/lo (weights)
__global__ void transpose_split512(const float* __restrict__ in,
                                   float* __restrict__ outf,
                                   __nv_bfloat16* __restrict__ hi,
                                   __nv_bfloat16* __restrict__ lo)
{
    __shared__ float t[32][33];
    const int bx = blockIdx.x * 32, by = blockIdx.y * 32;
    const int x = threadIdx.x, y = threadIdx.y;   // 32x8
    #pragma unroll
    for (int j = 0; j < 32; j += 8)
        t[y + j][x] = in[(size_t)(by + y + j) * 512 + bx + x];
    __syncthreads();
    #pragma unroll
    for (int j = 0; j < 32; j += 8) {
        const float v = t[x][y + j];
        const size_t p = (size_t)(bx + y + j) * 512 + by + x;
        outf[p] = v;
        const __nv_bfloat16 h = __float2bfloat16_rn(v);
        hi[p] = h;
        lo[p] = __float2bfloat16_rn(v - __bfloat162float(h));
    }
}

extern "C" void kernel_launch(void* const* d_in, const int* in_sizes, int n_in,
                              void* d_out, int out_size)
{
    const float* X   = (const float*)d_in[0];
    const float* adj = (const float*)d_in[1];
    const float* W0  = (const float*)d_in[2];
    const float* b0  = (const float*)d_in[3];
    const float* W1  = (const float*)d_in[4];
    const float* b1  = (const float*)d_in[5];
    const float* W2  = (const float*)d_in[6];
    const float* b2  = (const float*)d_in[7];
    float* out = (float*)d_out;

    __nv_bfloat16 *Xhi,*Xlo,*Jhi,*Jlo,*Shi,*Slo,*Hhi,*Hlo,*Wthi,*Wtlo;
    float *Sf,*Hf,*Wtf;
    cudaGetSymbolAddress((void**)&Xhi, g_Xhi);  cudaGetSymbolAddress((void**)&Xlo, g_Xlo);
    cudaGetSymbolAddress((void**)&Jhi, g_Jhi);  cudaGetSymbolAddress((void**)&Jlo, g_Jlo);
    cudaGetSymbolAddress((void**)&Shi, g_Shi);  cudaGetSymbolAddress((void**)&Slo, g_Slo);
    cudaGetSymbolAddress((void**)&Hhi, g_Hhi);  cudaGetSymbolAddress((void**)&Hlo, g_Hlo);
    cudaGetSymbolAddress((void**)&Wthi, g_Wthi); cudaGetSymbolAddress((void**)&Wtlo, g_Wtlo);
    cudaGetSymbolAddress((void**)&Sf, g_Sf);
    cudaGetSymbolAddress((void**)&Hf, g_Hf);
    cudaGetSymbolAddress((void**)&Wtf, g_Wtf);

    cudaFuncSetAttribute(hgemm<0>, cudaFuncAttributeMaxDynamicSharedMemorySize, SMEM_BYTES);
    cudaFuncSetAttribute(hgemm<1>, cudaFuncAttributeMaxDynamicSharedMemorySize, SMEM_BYTES);
    cudaFuncSetAttribute(hgemm<2>, cudaFuncAttributeMaxDynamicSharedMemorySize, SMEM_BYTES);

    const long s = 512l * 512l;
    const int n4 = (int)(NE / 4);
    split_f32<<<(n4 + 255) / 256, 256>>>(X,   Xhi, Xlo, n4);
    split_f32<<<(n4 + 255) / 256, 256>>>(adj, Jhi, Jlo, n4);
    const dim3 tgrid(16, 16), tblk(32, 8);
    transpose_split512<<<tgrid, tblk>>>(W0, Wtf + 0*s, Wthi + 0*s, Wtlo + 0*s);
    transpose_split512<<<tgrid, tblk>>>(W1, Wtf + 1*s, Wthi + 1*s, Wtlo + 1*s);
    transpose_split512<<<tgrid, tblk>>>(W2, Wtf + 2*s, Wthi + 2*s, Wtlo + 2*s);

    const dim3 grid(8, 4, 32), blk(256);
    // Layer 0:  S^T = (X @ W0)^T ;  H = relu(adj @ S + b0)
    hgemm<0><<<grid, blk, SMEM_BYTES>>>(Wthi + 0*s, Wtlo + 0*s, Wtf + 0*s,
                                        Xhi, Xlo, X,
                                        nullptr, Sf, Shi, Slo, 0, s);
    hgemm<1><<<grid, blk, SMEM_BYTES>>>(Jhi, Jlo, adj, Shi, Slo, Sf,
                                        b0, Hf, Hhi, Hlo, s, s);
    // Layer 1
    hgemm<0><<<grid, blk, SMEM_BYTES>>>(Wthi + 1*s, Wtlo + 1*s, Wtf + 1*s,
                                        Hhi, Hlo, Hf,
                                        nullptr, Sf, Shi, Slo, 0, s);
    hgemm<1><<<grid, blk, SMEM_BYTES>>>(Jhi, Jlo, adj, Shi, Slo, Sf,
                                        b1, Hf, Hhi, Hlo, s, s);
    // Layer 2 (no relu, fp32 out only)
    hgemm<0><<<grid, blk, SMEM_BYTES>>>(Wthi + 2*s, Wtlo + 2*s, Wtf + 2*s,
                                        Hhi, Hlo, Hf,
                                        nullptr, Sf, Shi, Slo, 0, s);
    hgemm<2><<<grid, blk, SMEM_BYTES>>>(Jhi, Jlo, adj, Shi, Slo, Sf,
                                        b2, out, nullptr, nullptr, s, s);
}

// round 11
// speedup vs baseline: 5.0970x; 2.2420x over previous
#include <cuda_runtime.h>
#include <cuda_fp16.h>
#include <cstdint>

// ============================================================
// GCN GEMMs with fp16 2-term split mma.sync (was bf16 3-term).
//   D = (A_hi + A_lo) * B_h      -> 2 MMAs per fp32 MAC (was 3)
// A-side (adj, W^T) split to fp16 hi+lo once up front (error 2^-22);
// B-side (X, intermediates) single fp16 (error ~2^-12.8 per hop).
// Dataflow (R7): intermediates are always the B operand.
//   feature GEMM:  S^T[j,i] = sum_k Wt[j,k] * H[i,k]   (EPI=0 -> fp16)
//   adj GEMM:      H'[i,e]  = sum_k adj[i,k]* S^T[e,k] (EPI=1 relu fp16, 2 fp32)
// ============================================================

static constexpr unsigned NE = 32u * 512u * 512u;
static constexpr unsigned NW = 512u * 512u;

static __device__ __half g_Xh[NE];                  // X as B operand
static __device__ __half g_Jhi[NE], g_Jlo[NE];      // adj split (A side)
static __device__ __half g_Sh[NE];                  // S^T intermediate (B side)
static __device__ __half g_Hh[NE];                  // H intermediate (B side)
static __device__ __half g_Wthi[3*NW], g_Wtlo[3*NW];

__device__ __forceinline__ uint32_t smem_u32(const void* p) {
    uint32_t a;
    asm("{ .reg .u64 t; cvta.to.shared.u64 t, %1; cvt.u32.u64 %0, t; }"
        : "=r"(a) : "l"(p));
    return a;
}

#define LDSM_X4(r0, r1, r2, r3, addr) \
    asm volatile("ldmatrix.sync.aligned.m8n8.x4.shared.b16 {%0,%1,%2,%3}, [%4];" \
                 : "=r"(r0), "=r"(r1), "=r"(r2), "=r"(r3) : "r"(addr))

#define CP_ASYNC16(dst, src) \
    asm volatile("cp.async.cg.shared.global [%0], [%1], 16;" \
                 :: "r"(dst), "l"(src) : "memory")
#define CP_COMMIT() asm volatile("cp.async.commit_group;" ::: "memory")
#define CP_WAIT(n)  asm volatile("cp.async.wait_group %0;" :: "n"(n) : "memory")

__device__ __forceinline__ void mma16816(float* d, const uint32_t* a,
                                         uint32_t b0, uint32_t b1) {
    asm volatile(
        "mma.sync.aligned.m16n8k16.row.col.f32.f16.f16.f32 "
        "{%0,%1,%2,%3}, {%4,%5,%6,%7}, {%8,%9}, {%0,%1,%2,%3};"
        : "+f"(d[0]), "+f"(d[1]), "+f"(d[2]), "+f"(d[3])
        : "r"(a[0]), "r"(a[1]), "r"(a[2]), "r"(a[3]), "r"(b0), "r"(b1));
}

// smem tile: 128 rows x 32 fp16 = 64B/row, XOR swizzle on 16B chunks
static constexpr int TILE  = 128 * 64;           // 8KB
static constexpr int OFF_AH = 0, OFF_AL = TILE, OFF_BH = 2 * TILE;
static constexpr int STAGE = 3 * TILE;           // 24KB
static constexpr int NSTG  = 3;
static constexpr int SMEM_BYTES = NSTG * STAGE;  // 72KB

__device__ __forceinline__ uint32_t sw_off(int row, int q) {
    return (uint32_t)row * 64u + (uint32_t)((q ^ ((row >> 1) & 3)) << 4);
}

// EPI: 0 = plain -> fp16, 1 = bias+relu -> fp16, 2 = bias -> fp32
template <int EPI>
__global__ __launch_bounds__(256, 2)
void hgemm(const __half* __restrict__ Ahi, const __half* __restrict__ Alo,
           const __half* __restrict__ Bh,
           const float* __restrict__ bias,
           float* __restrict__ Cf, __half* __restrict__ Ch,
           long strideA, long strideB)
{
    extern __shared__ char smem[];
    const uint32_t sb = smem_u32(smem);
    const int tid  = threadIdx.x;
    const int wid  = tid >> 5;
    const int lane = tid & 31;

    const long s = 512l * 512l;
    const size_t offA = (size_t)blockIdx.z * strideA;
    const size_t offB = (size_t)blockIdx.z * strideB;

    const int rowBlock = blockIdx.y * 128;
    const int colBlock = blockIdx.x * 128;

    const int wm = (wid >> 2) * 64;    // 2 warps in M
    const int wn = (wid & 3) * 32;     // 4 warps in N

    // cp.async geometry: 2 (row,q) chunks per tile per thread
    const int cQ = tid & 3;
    uint32_t dOf[2];
    size_t gA[2], gB[2];
    #pragma unroll
    for (int i = 0; i < 2; ++i) {
        const int row = (tid >> 2) + i * 64;
        dOf[i] = sw_off(row, cQ);
        gA[i] = offA + (size_t)(rowBlock + row) * 512 + cQ * 8;
        gB[i] = offB + (size_t)(colBlock + row) * 512 + cQ * 8;
    }

    auto issue = [&](int c) {
        const uint32_t st = sb + (uint32_t)(c % NSTG) * STAGE;
        const int k0 = c * 32;
        #pragma unroll
        for (int i = 0; i < 2; ++i) {
            CP_ASYNC16(st + OFF_AH + dOf[i], Ahi + gA[i] + k0);
            CP_ASYNC16(st + OFF_AL + dOf[i], Alo + gA[i] + k0);
            CP_ASYNC16(st + OFF_BH + dOf[i], Bh  + gB[i] + k0);
        }
        CP_COMMIT();
    };

    // ldmatrix geometry
    const int lmRow = lane & 15;
    const int lmQ   = lane >> 4;
    uint32_t aRow[4], bRow[2];
    int aXr[4], bXr[2];
    #pragma unroll
    for (int ti = 0; ti < 4; ++ti) {
        const int r = wm + ti * 16 + lmRow;
        aRow[ti] = (uint32_t)r * 64u;
        aXr[ti]  = (r >> 1) & 3;
    }
    #pragma unroll
    for (int g = 0; g < 2; ++g) {
        const int r = wn + g * 16 + lmRow;
        bRow[g] = (uint32_t)r * 64u;
        bXr[g]  = (r >> 1) & 3;
    }

    float acc[4][4][4] = {};

    issue(0);
    issue(1);

    for (int c = 0; c < 16; ++c) {
        if (c == 15) { CP_WAIT(0); } else { CP_WAIT(1); }
        __syncthreads();
        if (c + 2 < 16) issue(c + 2);

        const uint32_t st = sb + (uint32_t)(c % NSTG) * STAGE;

        #pragma unroll
        for (int kk = 0; kk < 2; ++kk) {
            const int q = lmQ + kk * 2;
            uint32_t af[4][4], bb[2][4];
            #pragma unroll
            for (int g = 0; g < 2; ++g) {
                const uint32_t sw = (uint32_t)((q ^ bXr[g]) << 4);
                LDSM_X4(bb[g][0], bb[g][1], bb[g][2], bb[g][3],
                        st + OFF_BH + bRow[g] + sw);
            }
            // A hi -> hh
            #pragma unroll
            for (int ti = 0; ti < 4; ++ti) {
                const uint32_t sw = (uint32_t)((q ^ aXr[ti]) << 4);
                LDSM_X4(af[ti][0], af[ti][1], af[ti][2], af[ti][3],
                        st + OFF_AH + aRow[ti] + sw);
            }
            #pragma unroll
            for (int ti = 0; ti < 4; ++ti)
                #pragma unroll
                for (int tj = 0; tj < 4; ++tj)
                    mma16816(acc[ti][tj], af[ti],
                             bb[tj >> 1][tj & 1], bb[tj >> 1][2 + (tj & 1)]);
            // A lo (overwrite hi frags) -> lh
            #pragma unroll
            for (int ti = 0; ti < 4; ++ti) {
                const uint32_t sw = (uint32_t)((q ^ aXr[ti]) << 4);
                LDSM_X4(af[ti][0], af[ti][1], af[ti][2], af[ti][3],
                        st + OFF_AL + aRow[ti] + sw);
            }
            #pragma unroll
            for (int ti = 0; ti < 4; ++ti)
                #pragma unroll
                for (int tj = 0; tj < 4; ++tj)
                    mma16816(acc[ti][tj], af[ti],
                             bb[tj >> 1][tj & 1], bb[tj >> 1][2 + (tj & 1)]);
        }
    }

    // epilogue
    const size_t offC = (size_t)blockIdx.z * s;
    #pragma unroll
    for (int ti = 0; ti < 4; ++ti) {
        const int m0 = rowBlock + wm + ti * 16 + (lane >> 2);
        #pragma unroll
        for (int tj = 0; tj < 4; ++tj) {
            const int n0 = colBlock + wn + tj * 8 + (lane & 3) * 2;
            float2 v0 = make_float2(acc[ti][tj][0], acc[ti][tj][1]);
            float2 v1 = make_float2(acc[ti][tj][2], acc[ti][tj][3]);
            if (EPI != 0) {
                const float bx = __ldg(bias + n0), by = __ldg(bias + n0 + 1);
                v0.x += bx; v0.y += by; v1.x += bx; v1.y += by;
                if (EPI == 1) {
                    v0.x = fmaxf(v0.x, 0.f); v0.y = fmaxf(v0.y, 0.f);
                    v1.x = fmaxf(v1.x, 0.f); v1.y = fmaxf(v1.y, 0.f);
                }
            }
            const size_t p0 = offC + (size_t)m0 * 512 + n0;
            const size_t p1 = p0 + 8 * 512;
            if (EPI == 2) {
                *(float2*)(Cf + p0) = v0;
                *(float2*)(Cf + p1) = v1;
            } else {
                __half2 h0 = __floats2half2_rn(v0.x, v0.y);
                __half2 h1 = __floats2half2_rn(v1.x, v1.y);
                *(uint32_t*)(Ch + p0) = *(uint32_t*)&h0;
                *(uint32_t*)(Ch + p1) = *(uint32_t*)&h1;
            }
        }
    }
}

// fp32 -> fp16 (B-side single)
__global__ __launch_bounds__(256)
void f2h(const float* __restrict__ in, __half* __restrict__ out, int n4)
{
    const int i = blockIdx.x * blockDim.x + threadIdx.x;
    if (i >= n4) return;
    float4 v = ((const float4*)in)[i];
    __half2 h0 = __floats2half2_rn(v.x, v.y);
    __half2 h1 = __floats2half2_rn(v.z, v.w);
    ((uint2*)out)[i] = make_uint2(*(uint32_t*)&h0, *(uint32_t*)&h1);
}

// fp32 -> fp16 hi + lo (A-side split)
__global__ __launch_bounds__(256)
void split_pair(const float* __restrict__ in,
                __half* __restrict__ hi, __half* __restrict__ lo, int n4)
{
    const int i = blockIdx.x * blockDim.x + threadIdx.x;
    if (i >= n4) return;
    float4 v = ((const float4*)in)[i];
    __half hx = __float2half_rn(v.x), hy = __float2half_rn(v.y);
    __half hz = __float2half_rn(v.z), hw = __float2half_rn(v.w);
    __half2 h0, h1, l0, l1;
    h0.x = hx; h0.y = hy; h1.x = hz; h1.y = hw;
    l0.x = __float2half_rn(v.x - __half2float(hx));
    l0.y = __float2half_rn(v.y - __half2float(hy));
    l1.x = __float2half_rn(v.z - __half2float(hz));
    l1.y = __float2half_rn(v.w - __half2float(hw));
    ((uint2*)hi)[i] = make_uint2(*(uint32_t*)&h0, *(uint32_t*)&h1);
    ((uint2*)lo)[i] = make_uint2(*(uint32_t*)&l0, *(uint32_t*)&l1);
}

// transpose 512x512 fp32 -> fp16 hi/lo (weights, A-side)
__global__ void transpose_split512(const float* __restrict__ in,
                                   __half* __restrict__ hi,
                                   __half* __restrict__ lo)
{
    __shared__ float t[32][33];
    const int bx = blockIdx.x * 32, by = blockIdx.y * 32;
    const int x = threadIdx.x, y = threadIdx.y;   // 32x8
    #pragma unroll
    for (int j = 0; j < 32; j += 8)
        t[y + j][x] = in[(size_t)(by + y + j) * 512 + bx + x];
    __syncthreads();
    #pragma unroll
    for (int j = 0; j < 32; j += 8) {
        const float v = t[x][y + j];
        const size_t p = (size_t)(bx + y + j) * 512 + by + x;
        const __half h = __float2half_rn(v);
        hi[p] = h;
        lo[p] = __float2half_rn(v - __half2float(h));
    }
}

extern "C" void kernel_launch(void* const* d_in, const int* in_sizes, int n_in,
                              void* d_out, int out_size)
{
    const float* X   = (const float*)d_in[0];
    const float* adj = (const float*)d_in[1];
    const float* W0  = (const float*)d_in[2];
    const float* b0  = (const float*)d_in[3];
    const float* W1  = (const float*)d_in[4];
    const float* b1  = (const float*)d_in[5];
    const float* W2  = (const float*)d_in[6];
    const float* b2  = (const float*)d_in[7];
    float* out = (float*)d_out;

    __half *Xh, *Jhi, *Jlo, *Sh, *Hh, *Wthi, *Wtlo;
    cudaGetSymbolAddress((void**)&Xh,  g_Xh);
    cudaGetSymbolAddress((void**)&Jhi, g_Jhi);
    cudaGetSymbolAddress((void**)&Jlo, g_Jlo);
    cudaGetSymbolAddress((void**)&Sh,  g_Sh);
    cudaGetSymbolAddress((void**)&Hh,  g_Hh);
    cudaGetSymbolAddress((void**)&Wthi, g_Wthi);
    cudaGetSymbolAddress((void**)&Wtlo, g_Wtlo);

    cudaFuncSetAttribute(hgemm<0>, cudaFuncAttributeMaxDynamicSharedMemorySize, SMEM_BYTES);
    cudaFuncSetAttribute(hgemm<1>, cudaFuncAttributeMaxDynamicSharedMemorySize, SMEM_BYTES);
    cudaFuncSetAttribute(hgemm<2>, cudaFuncAttributeMaxDynamicSharedMemorySize, SMEM_BYTES);

    const long s = 512l * 512l;
    const int n4 = (int)(NE / 4);
    f2h<<<(n4 + 255) / 256, 256>>>(X, Xh, n4);
    split_pair<<<(n4 + 255) / 256, 256>>>(adj, Jhi, Jlo, n4);
    const dim3 tgrid(16, 16), tblk(32, 8);
    transpose_split512<<<tgrid, tblk>>>(W0, Wthi + 0 * s, Wtlo + 0 * s);
    transpose_split512<<<tgrid, tblk>>>(W1, Wthi + 1 * s, Wtlo + 1 * s);
    transpose_split512<<<tgrid, tblk>>>(W2, Wthi + 2 * s, Wtlo + 2 * s);

    const dim3 grid(4, 4, 32), blk(256);
    // Layer 0:  S^T = (X @ W0)^T  (A=Wt0 split, B=Xh) ; H = relu(adj @ S + b0)
    hgemm<0><<<grid, blk, SMEM_BYTES>>>(Wthi + 0*s, Wtlo + 0*s, Xh,
                                        nullptr, nullptr, Sh, 0, s);
    hgemm<1><<<grid, blk, SMEM_BYTES>>>(Jhi, Jlo, Sh, b0, nullptr, Hh, s, s);
    // Layer 1
    hgemm<0><<<grid, blk, SMEM_BYTES>>>(Wthi + 1*s, Wtlo + 1*s, Hh,
                                        nullptr, nullptr, Sh, 0, s);
    hgemm<1><<<grid, blk, SMEM_BYTES>>>(Jhi, Jlo, Sh, b1, nullptr, Hh, s, s);
    // Layer 2 (no relu, fp32 out)
    hgemm<0><<<grid, blk, SMEM_BYTES>>>(Wthi + 2*s, Wtlo + 2*s, Hh,
                                        nullptr, nullptr, Sh, 0, s);
    hgemm<2><<<grid, blk, SMEM_BYTES>>>(Jhi, Jlo, Sh, b2, out, nullptr, s, s);
}

// round 12
// speedup vs baseline: 9.1102x; 1.7874x over previous
#include <cuda_runtime.h>
#include <cuda_fp16.h>
#include <cstdint>

// ============================================================
// GCN GEMMs, all-fp16 single-term mma.sync (1 MMA per fp32 MAC).
// R10 measured the 2-term error at 2.5e-4; quantizing the A side too
// adds ~sqrt(2)x -> ~3.5-4.5e-4, inside the 1e-3 gate, and halves
// the tensor work (HMMA floor ~178us).
//   feature GEMM:  S^T[j,i] = sum_k Wt[j,k] * H[i,k]   (EPI=0 -> fp16)
//   adj GEMM:      H'[i,e]  = sum_k adj[i,k]* S^T[e,k] (EPI=1 relu fp16, 2 fp32)
// ============================================================

static constexpr unsigned NE = 32u * 512u * 512u;
static constexpr unsigned NW = 512u * 512u;

static __device__ __half g_Xh[NE];            // X (B side)
static __device__ __half g_Jh[NE];            // adj (A side)
static __device__ __half g_Sh[NE];            // S^T intermediate
static __device__ __half g_Hh[NE];            // H intermediate
static __device__ __half g_Wth[3*NW];         // W^T x3 (A side)

__device__ __forceinline__ uint32_t smem_u32(const void* p) {
    uint32_t a;
    asm("{ .reg .u64 t; cvta.to.shared.u64 t, %1; cvt.u32.u64 %0, t; }"
        : "=r"(a) : "l"(p));
    return a;
}

#define LDSM_X4(r0, r1, r2, r3, addr) \
    asm volatile("ldmatrix.sync.aligned.m8n8.x4.shared.b16 {%0,%1,%2,%3}, [%4];" \
                 : "=r"(r0), "=r"(r1), "=r"(r2), "=r"(r3) : "r"(addr))

#define CP_ASYNC16(dst, src) \
    asm volatile("cp.async.cg.shared.global [%0], [%1], 16;" \
                 :: "r"(dst), "l"(src) : "memory")
#define CP_COMMIT() asm volatile("cp.async.commit_group;" ::: "memory")
#define CP_WAIT(n)  asm volatile("cp.async.wait_group %0;" :: "n"(n) : "memory")

__device__ __forceinline__ void mma16816(float* d, const uint32_t* a,
                                         uint32_t b0, uint32_t b1) {
    asm volatile(
        "mma.sync.aligned.m16n8k16.row.col.f32.f16.f16.f32 "
        "{%0,%1,%2,%3}, {%4,%5,%6,%7}, {%8,%9}, {%0,%1,%2,%3};"
        : "+f"(d[0]), "+f"(d[1]), "+f"(d[2]), "+f"(d[3])
        : "r"(a[0]), "r"(a[1]), "r"(a[2]), "r"(a[3]), "r"(b0), "r"(b1));
}

// smem tile: 128 rows x 32 fp16 = 64B/row, XOR swizzle on 16B chunks
static constexpr int TILE  = 128 * 64;           // 8KB
static constexpr int OFF_A = 0, OFF_B = TILE;
static constexpr int STAGE = 2 * TILE;           // 16KB
static constexpr int NSTG  = 3;
static constexpr int SMEM_BYTES = NSTG * STAGE;  // 48KB

__device__ __forceinline__ uint32_t sw_off(int row, int q) {
    return (uint32_t)row * 64u + (uint32_t)((q ^ ((row >> 1) & 3)) << 4);
}

// EPI: 0 = plain -> fp16, 1 = bias+relu -> fp16, 2 = bias -> fp32
template <int EPI>
__global__ __launch_bounds__(256, 2)
void hgemm(const __half* __restrict__ Ah, const __half* __restrict__ Bh,
           const float* __restrict__ bias,
           float* __restrict__ Cf, __half* __restrict__ Ch,
           long strideA, long strideB)
{
    extern __shared__ char smem[];
    const uint32_t sb = smem_u32(smem);
    const int tid  = threadIdx.x;
    const int wid  = tid >> 5;
    const int lane = tid & 31;

    const long s = 512l * 512l;
    const size_t offA = (size_t)blockIdx.z * strideA;
    const size_t offB = (size_t)blockIdx.z * strideB;

    const int rowBlock = blockIdx.y * 128;
    const int colBlock = blockIdx.x * 128;

    const int wm = (wid >> 2) * 64;    // 2 warps in M
    const int wn = (wid & 3) * 32;     // 4 warps in N

    // cp.async geometry: 2 (row,q) chunks per tile per thread
    const int cQ = tid & 3;
    uint32_t dOf[2];
    size_t gA[2], gB[2];
    #pragma unroll
    for (int i = 0; i < 2; ++i) {
        const int row = (tid >> 2) + i * 64;
        dOf[i] = sw_off(row, cQ);
        gA[i] = offA + (size_t)(rowBlock + row) * 512 + cQ * 8;
        gB[i] = offB + (size_t)(colBlock + row) * 512 + cQ * 8;
    }

    auto issue = [&](int c) {
        const uint32_t st = sb + (uint32_t)(c % NSTG) * STAGE;
        const int k0 = c * 32;
        #pragma unroll
        for (int i = 0; i < 2; ++i) {
            CP_ASYNC16(st + OFF_A + dOf[i], Ah + gA[i] + k0);
            CP_ASYNC16(st + OFF_B + dOf[i], Bh + gB[i] + k0);
        }
        CP_COMMIT();
    };

    // ldmatrix geometry
    const int lmRow = lane & 15;
    const int lmQ   = lane >> 4;
    uint32_t aRow[4], bRow[2];
    int aXr[4], bXr[2];
    #pragma unroll
    for (int ti = 0; ti < 4; ++ti) {
        const int r = wm + ti * 16 + lmRow;
        aRow[ti] = (uint32_t)r * 64u;
        aXr[ti]  = (r >> 1) & 3;
    }
    #pragma unroll
    for (int g = 0; g < 2; ++g) {
        const int r = wn + g * 16 + lmRow;
        bRow[g] = (uint32_t)r * 64u;
        bXr[g]  = (r >> 1) & 3;
    }

    float acc[4][4][4] = {};

    issue(0);
    issue(1);

    for (int c = 0; c < 16; ++c) {
        if (c == 15) { CP_WAIT(0); } else { CP_WAIT(1); }
        __syncthreads();
        if (c + 2 < 16) issue(c + 2);

        const uint32_t st = sb + (uint32_t)(c % NSTG) * STAGE;

        #pragma unroll
        for (int kk = 0; kk < 2; ++kk) {
            const int q = lmQ + kk * 2;
            uint32_t af[4][4], bb[2][4];
            #pragma unroll
            for (int g = 0; g < 2; ++g) {
                const uint32_t sw = (uint32_t)((q ^ bXr[g]) << 4);
                LDSM_X4(bb[g][0], bb[g][1], bb[g][2], bb[g][3],
                        st + OFF_B + bRow[g] + sw);
            }
            #pragma unroll
            for (int ti = 0; ti < 4; ++ti) {
                const uint32_t sw = (uint32_t)((q ^ aXr[ti]) << 4);
                LDSM_X4(af[ti][0], af[ti][1], af[ti][2], af[ti][3],
                        st + OFF_A + aRow[ti] + sw);
            }
            #pragma unroll
            for (int ti = 0; ti < 4; ++ti)
                #pragma unroll
                for (int tj = 0; tj < 4; ++tj)
                    mma16816(acc[ti][tj], af[ti],
                             bb[tj >> 1][tj & 1], bb[tj >> 1][2 + (tj & 1)]);
        }
    }

    // epilogue
    const size_t offC = (size_t)blockIdx.z * s;
    #pragma unroll
    for (int ti = 0; ti < 4; ++ti) {
        const int m0 = rowBlock + wm + ti * 16 + (lane >> 2);
        #pragma unroll
        for (int tj = 0; tj < 4; ++tj) {
            const int n0 = colBlock + wn + tj * 8 + (lane & 3) * 2;
            float2 v0 = make_float2(acc[ti][tj][0], acc[ti][tj][1]);
            float2 v1 = make_float2(acc[ti][tj][2], acc[ti][tj][3]);
            if (EPI != 0) {
                const float bx = __ldg(bias + n0), by = __ldg(bias + n0 + 1);
                v0.x += bx; v0.y += by; v1.x += bx; v1.y += by;
                if (EPI == 1) {
                    v0.x = fmaxf(v0.x, 0.f); v0.y = fmaxf(v0.y, 0.f);
                    v1.x = fmaxf(v1.x, 0.f); v1.y = fmaxf(v1.y, 0.f);
                }
            }
            const size_t p0 = offC + (size_t)m0 * 512 + n0;
            const size_t p1 = p0 + 8 * 512;
            if (EPI == 2) {
                *(float2*)(Cf + p0) = v0;
                *(float2*)(Cf + p1) = v1;
            } else {
                __half2 h0 = __floats2half2_rn(v0.x, v0.y);
                __half2 h1 = __floats2half2_rn(v1.x, v1.y);
                *(uint32_t*)(Ch + p0) = *(uint32_t*)&h0;
                *(uint32_t*)(Ch + p1) = *(uint32_t*)&h1;
            }
        }
    }
}

// fp32 -> fp16
__global__ __launch_bounds__(256)
void f2h(const float* __restrict__ in, __half* __restrict__ out, int n4)
{
    const int i = blockIdx.x * blockDim.x + threadIdx.x;
    if (i >= n4) return;
    float4 v = ((const float4*)in)[i];
    __half2 h0 = __floats2half2_rn(v.x, v.y);
    __half2 h1 = __floats2half2_rn(v.z, v.w);
    ((uint2*)out)[i] = make_uint2(*(uint32_t*)&h0, *(uint32_t*)&h1);
}

// transpose 512x512 fp32 -> fp16 (weights)
__global__ void transpose_h512(const float* __restrict__ in,
                               __half* __restrict__ out)
{
    __shared__ float t[32][33];
    const int bx = blockIdx.x * 32, by = blockIdx.y * 32;
    const int x = threadIdx.x, y = threadIdx.y;   // 32x8
    #pragma unroll
    for (int j = 0; j < 32; j += 8)
        t[y + j][x] = in[(size_t)(by + y + j) * 512 + bx + x];
    __syncthreads();
    #pragma unroll
    for (int j = 0; j < 32; j += 8)
        out[(size_t)(bx + y + j) * 512 + by + x] = __float2half_rn(t[x][y + j]);
}

extern "C" void kernel_launch(void* const* d_in, const int* in_sizes, int n_in,
                              void* d_out, int out_size)
{
    const float* X   = (const float*)d_in[0];
    const float* adj = (const float*)d_in[1];
    const float* W0  = (const float*)d_in[2];
    const float* b0  = (const float*)d_in[3];
    const float* W1  = (const float*)d_in[4];
    const float* b1  = (const float*)d_in[5];
    const float* W2  = (const float*)d_in[6];
    const float* b2  = (const float*)d_in[7];
    float* out = (float*)d_out;

    __half *Xh, *Jh, *Sh, *Hh, *Wth;
    cudaGetSymbolAddress((void**)&Xh,  g_Xh);
    cudaGetSymbolAddress((void**)&Jh,  g_Jh);
    cudaGetSymbolAddress((void**)&Sh,  g_Sh);
    cudaGetSymbolAddress((void**)&Hh,  g_Hh);
    cudaGetSymbolAddress((void**)&Wth, g_Wth);

    cudaFuncSetAttribute(hgemm<0>, cudaFuncAttributeMaxDynamicSharedMemorySize, SMEM_BYTES);
    cudaFuncSetAttribute(hgemm<1>, cudaFuncAttributeMaxDynamicSharedMemorySize, SMEM_BYTES);
    cudaFuncSetAttribute(hgemm<2>, cudaFuncAttributeMaxDynamicSharedMemorySize, SMEM_BYTES);

    const long s = 512l * 512l;
    const int n4 = (int)(NE / 4);
    f2h<<<(n4 + 255) / 256, 256>>>(X,   Xh, n4);
    f2h<<<(n4 + 255) / 256, 256>>>(adj, Jh, n4);
    const dim3 tgrid(16, 16), tblk(32, 8);
    transpose_h512<<<tgrid, tblk>>>(W0, Wth + 0 * s);
    transpose_h512<<<tgrid, tblk>>>(W1, Wth + 1 * s);
    transpose_h512<<<tgrid, tblk>>>(W2, Wth + 2 * s);

    const dim3 grid(4, 4, 32), blk(256);
    // Layer 0:  S^T = (X @ W0)^T  (A=Wt0, B=Xh) ; H = relu(adj @ S + b0)
    hgemm<0><<<grid, blk, SMEM_BYTES>>>(Wth + 0*s, Xh, nullptr, nullptr, Sh, 0, s);
    hgemm<1><<<grid, blk, SMEM_BYTES>>>(Jh, Sh, b0, nullptr, Hh, s, s);
    // Layer 1
    hgemm<0><<<grid, blk, SMEM_BYTES>>>(Wth + 1*s, Hh, nullptr, nullptr, Sh, 0, s);
    hgemm<1><<<grid, blk, SMEM_BYTES>>>(Jh, Sh, b1, nullptr, Hh, s, s);
    // Layer 2 (no relu, fp32 out)
    hgemm<0><<<grid, blk, SMEM_BYTES>>>(Wth + 2*s, Hh, nullptr, nullptr, Sh, 0, s);
    hgemm<2><<<grid, blk, SMEM_BYTES>>>(Jh, Sh, b2, out, nullptr, s, s);
}

// round 13
// speedup vs baseline: 9.3827x; 1.0299x over previous
#include <cuda_runtime.h>
#include <cuda_fp16.h>
#include <cstdint>

// ============================================================
// GCN, all-fp16 mma.sync, ONE persistent kernel for all 6 GEMMs.
// 296 CTAs (all resident, 2/SM), 3072 tiles stage-major, static
// stripe; cross-stage deps via per-(stage,z,rowblock) counters
// (tile needs cnt[s-1][z][cb]==4). Distinct inter-stage buffers
// (Sa,Ha,Sb,Hb,Sc) -> no WAR. Preproc fused into one launch.
// ============================================================

static constexpr unsigned NE = 32u * 512u * 512u;
static constexpr unsigned NW = 512u * 512u;
static constexpr int NCTA = 296;                 // 2 x 148 (safe on 148/152 SMs)

static __device__ __half g_Xh[NE], g_Jh[NE];
static __device__ __half g_Sa[NE], g_Ha[NE], g_Sb[NE], g_Hb[NE], g_Sc[NE];
static __device__ __half g_Wth[3 * NW];
static __device__ int    g_cnt[6 * 32 * 4];

__device__ __forceinline__ uint32_t smem_u32(const void* p) {
    uint32_t a;
    asm("{ .reg .u64 t; cvta.to.shared.u64 t, %1; cvt.u32.u64 %0, t; }"
        : "=r"(a) : "l"(p));
    return a;
}

#define LDSM_X4(r0, r1, r2, r3, addr) \
    asm volatile("ldmatrix.sync.aligned.m8n8.x4.shared.b16 {%0,%1,%2,%3}, [%4];" \
                 : "=r"(r0), "=r"(r1), "=r"(r2), "=r"(r3) : "r"(addr))

#define CP_ASYNC16(dst, src) \
    asm volatile("cp.async.cg.shared.global [%0], [%1], 16;" \
                 :: "r"(dst), "l"(src) : "memory")
#define CP_COMMIT() asm volatile("cp.async.commit_group;" ::: "memory")
#define CP_WAIT(n)  asm volatile("cp.async.wait_group %0;" :: "n"(n) : "memory")

__device__ __forceinline__ void mma16816(float* d, const uint32_t* a,
                                         uint32_t b0, uint32_t b1) {
    asm volatile(
        "mma.sync.aligned.m16n8k16.row.col.f32.f16.f16.f32 "
        "{%0,%1,%2,%3}, {%4,%5,%6,%7}, {%8,%9}, {%0,%1,%2,%3};"
        : "+f"(d[0]), "+f"(d[1]), "+f"(d[2]), "+f"(d[3])
        : "r"(a[0]), "r"(a[1]), "r"(a[2]), "r"(a[3]), "r"(b0), "r"(b1));
}

static constexpr int TILE  = 128 * 64;           // 8KB (128 rows x 32 fp16)
static constexpr int OFF_A = 0, OFF_B = TILE;
static constexpr int STAGE_B = 2 * TILE;         // 16KB
static constexpr int NSTG  = 3;
static constexpr int SMEM_BYTES = NSTG * STAGE_B; // 48KB

__device__ __forceinline__ uint32_t sw_off(int row, int q) {
    return (uint32_t)row * 64u + (uint32_t)((q ^ ((row >> 1) & 3)) << 4);
}

// one 128x128 GEMM tile; epi: 0 plain->fp16, 1 bias+relu->fp16, 2 bias->fp32
__device__ __forceinline__
void gemm_tile(const __half* __restrict__ Ah, const __half* __restrict__ Bh,
               const float* __restrict__ bias,
               float* __restrict__ Cf, __half* __restrict__ Ch,
               long strideA, int z, int rb, int cb, int epi, uint32_t sb)
{
    const int tid  = threadIdx.x;
    const int wid  = tid >> 5;
    const int lane = tid & 31;
    const long s = 512l * 512l;
    const size_t offA = (size_t)z * strideA;
    const size_t offB = (size_t)z * s;
    const int rowBlock = rb * 128;
    const int colBlock = cb * 128;
    const int wm = (wid >> 2) * 64;
    const int wn = (wid & 3) * 32;

    const int cQ = tid & 3;
    uint32_t dOf[2];
    size_t gA[2], gB[2];
    #pragma unroll
    for (int i = 0; i < 2; ++i) {
        const int row = (tid >> 2) + i * 64;
        dOf[i] = sw_off(row, cQ);
        gA[i] = offA + (size_t)(rowBlock + row) * 512 + cQ * 8;
        gB[i] = offB + (size_t)(colBlock + row) * 512 + cQ * 8;
    }

    auto issue = [&](int c) {
        const uint32_t st = sb + (uint32_t)(c % NSTG) * STAGE_B;
        const int k0 = c * 32;
        #pragma unroll
        for (int i = 0; i < 2; ++i) {
            CP_ASYNC16(st + OFF_A + dOf[i], Ah + gA[i] + k0);
            CP_ASYNC16(st + OFF_B + dOf[i], Bh + gB[i] + k0);
        }
        CP_COMMIT();
    };

    const int lmRow = lane & 15;
    const int lmQ   = lane >> 4;
    uint32_t aRow[4], bRow[2];
    int aXr[4], bXr[2];
    #pragma unroll
    for (int ti = 0; ti < 4; ++ti) {
        const int r = wm + ti * 16 + lmRow;
        aRow[ti] = (uint32_t)r * 64u;
        aXr[ti]  = (r >> 1) & 3;
    }
    #pragma unroll
    for (int g = 0; g < 2; ++g) {
        const int r = wn + g * 16 + lmRow;
        bRow[g] = (uint32_t)r * 64u;
        bXr[g]  = (r >> 1) & 3;
    }

    float acc[4][4][4] = {};

    issue(0);
    issue(1);

    for (int c = 0; c < 16; ++c) {
        if (c == 15) { CP_WAIT(0); } else { CP_WAIT(1); }
        __syncthreads();
        if (c + 2 < 16) issue(c + 2);

        const uint32_t st = sb + (uint32_t)(c % NSTG) * STAGE_B;

        #pragma unroll
        for (int kk = 0; kk < 2; ++kk) {
            const int q = lmQ + kk * 2;
            uint32_t af[4][4], bb[2][4];
            #pragma unroll
            for (int g = 0; g < 2; ++g) {
                const uint32_t sw = (uint32_t)((q ^ bXr[g]) << 4);
                LDSM_X4(bb[g][0], bb[g][1], bb[g][2], bb[g][3],
                        st + OFF_B + bRow[g] + sw);
            }
            #pragma unroll
            for (int ti = 0; ti < 4; ++ti) {
                const uint32_t sw = (uint32_t)((q ^ aXr[ti]) << 4);
                LDSM_X4(af[ti][0], af[ti][1], af[ti][2], af[ti][3],
                        st + OFF_A + aRow[ti] + sw);
            }
            #pragma unroll
            for (int ti = 0; ti < 4; ++ti)
                #pragma unroll
                for (int tj = 0; tj < 4; ++tj)
                    mma16816(acc[ti][tj], af[ti],
                             bb[tj >> 1][tj & 1], bb[tj >> 1][2 + (tj & 1)]);
        }
        __syncthreads();   // stage slot reused next iter; keep pipeline sane
    }

    const size_t offC = (size_t)z * s;
    #pragma unroll
    for (int ti = 0; ti < 4; ++ti) {
        const int m0 = rowBlock + wm + ti * 16 + (lane >> 2);
        #pragma unroll
        for (int tj = 0; tj < 4; ++tj) {
            const int n0 = colBlock + wn + tj * 8 + (lane & 3) * 2;
            float2 v0 = make_float2(acc[ti][tj][0], acc[ti][tj][1]);
            float2 v1 = make_float2(acc[ti][tj][2], acc[ti][tj][3]);
            if (epi != 0) {
                const float bx = __ldg(bias + n0), by = __ldg(bias + n0 + 1);
                v0.x += bx; v0.y += by; v1.x += bx; v1.y += by;
                if (epi == 1) {
                    v0.x = fmaxf(v0.x, 0.f); v0.y = fmaxf(v0.y, 0.f);
                    v1.x = fmaxf(v1.x, 0.f); v1.y = fmaxf(v1.y, 0.f);
                }
            }
            const size_t p0 = offC + (size_t)m0 * 512 + n0;
            const size_t p1 = p0 + 8 * 512;
            if (epi == 2) {
                *(float2*)(Cf + p0) = v0;
                *(float2*)(Cf + p1) = v1;
            } else {
                __half2 h0 = __floats2half2_rn(v0.x, v0.y);
                __half2 h1 = __floats2half2_rn(v1.x, v1.y);
                *(uint32_t*)(Ch + p0) = *(uint32_t*)&h0;
                *(uint32_t*)(Ch + p1) = *(uint32_t*)&h1;
            }
        }
    }
}

__global__ __launch_bounds__(256, 2)
void gcn_persistent(const __half* __restrict__ Xh, const __half* __restrict__ Jh,
                    const __half* __restrict__ Wth,
                    __half* __restrict__ Sa, __half* __restrict__ Ha,
                    __half* __restrict__ Sb, __half* __restrict__ Hb,
                    __half* __restrict__ Sc,
                    const float* __restrict__ b0, const float* __restrict__ b1,
                    const float* __restrict__ b2,
                    float* __restrict__ out, int* __restrict__ cnt)
{
    extern __shared__ char smem[];
    const uint32_t sb = smem_u32(smem);
    const int tid = threadIdx.x;
    const long s = 512l * 512l;

    const __half* Ap[6] = {Wth, Jh, Wth + s, Jh, Wth + 2 * s, Jh};
    const long    sA[6] = {0, s, 0, s, 0, s};
    const __half* Bp[6] = {Xh, Sa, Ha, Sb, Hb, Sc};
    __half*       Cp[6] = {Sa, Ha, Sb, Hb, Sc, nullptr};
    const float*  bi[6] = {nullptr, b0, nullptr, b1, nullptr, b2};
    const int     ep[6] = {0, 1, 0, 1, 0, 2};

    for (int g = blockIdx.x; g < 6 * 512; g += NCTA) {
        const int stage = g >> 9;
        const int t = g & 511;
        const int z  = t >> 4;
        const int rb = (t >> 2) & 3;
        const int cb = t & 3;

        if (stage > 0) {
            if (tid == 0) {
                volatile int* c = cnt + ((stage - 1) * 32 + z) * 4 + cb;
                while (*c < 4) __nanosleep(32);
            }
            __syncthreads();
            __threadfence();   // acquire published data
        }

        gemm_tile(Ap[stage], Bp[stage], bi[stage], out, Cp[stage],
                  sA[stage], z, rb, cb, ep[stage], sb);

        __threadfence();       // publish tile stores
        __syncthreads();       // all threads' stores fenced before count
        if (tid == 0)
            atomicAdd(cnt + (stage * 32 + z) * 4 + rb, 1);
    }
}

// fused preprocessing: f2h(X), f2h(adj), transpose_h x3, one launch
__global__ __launch_bounds__(256)
void preproc(const float* __restrict__ X, const float* __restrict__ adj,
             const float* __restrict__ W0, const float* __restrict__ W1,
             const float* __restrict__ W2,
             __half* __restrict__ Xh, __half* __restrict__ Jh,
             __half* __restrict__ Wth)
{
    const int b = blockIdx.x;
    const int tid = threadIdx.x;
    const long s = 512l * 512l;

    if (b < 16384) {   // f2h: 2M float4 each for X and adj
        const bool isX = b < 8192;
        const float* in = isX ? X : adj;
        __half* o = isX ? Xh : Jh;
        const int i = (b & 8191) * 256 + tid;
        float4 v = ((const float4*)in)[i];
        __half2 h0 = __floats2half2_rn(v.x, v.y);
        __half2 h1 = __floats2half2_rn(v.z, v.w);
        ((uint2*)o)[i] = make_uint2(*(uint32_t*)&h0, *(uint32_t*)&h1);
        return;
    }
    // transpose: 3 x 256 blocks of 32x32 tiles
    const int tb = b - 16384;
    const int w  = tb >> 8;            // which weight
    const int ti = tb & 255;
    const float* in = (w == 0) ? W0 : (w == 1) ? W1 : W2;
    __half* o = Wth + (size_t)w * s;
    const int bx = (ti & 15) * 32, by = (ti >> 4) * 32;
    const int x = tid & 31, y = tid >> 5;   // 32x8
    __shared__ float t[32][33];
    #pragma unroll
    for (int j = 0; j < 32; j += 8)
        t[y + j][x] = in[(size_t)(by + y + j) * 512 + bx + x];
    __syncthreads();
    #pragma unroll
    for (int j = 0; j < 32; j += 8)
        o[(size_t)(bx + y + j) * 512 + by + x] = __float2half_rn(t[x][y + j]);
}

extern "C" void kernel_launch(void* const* d_in, const int* in_sizes, int n_in,
                              void* d_out, int out_size)
{
    const float* X   = (const float*)d_in[0];
    const float* adj = (const float*)d_in[1];
    const float* W0  = (const float*)d_in[2];
    const float* b0  = (const float*)d_in[3];
    const float* W1  = (const float*)d_in[4];
    const float* b1  = (const float*)d_in[5];
    const float* W2  = (const float*)d_in[6];
    const float* b2  = (const float*)d_in[7];
    float* out = (float*)d_out;

    __half *Xh, *Jh, *Sa, *Ha, *Sb, *Hb, *Sc, *Wth;
    int* cnt;
    cudaGetSymbolAddress((void**)&Xh,  g_Xh);
    cudaGetSymbolAddress((void**)&Jh,  g_Jh);
    cudaGetSymbolAddress((void**)&Sa,  g_Sa);
    cudaGetSymbolAddress((void**)&Ha,  g_Ha);
    cudaGetSymbolAddress((void**)&Sb,  g_Sb);
    cudaGetSymbolAddress((void**)&Hb,  g_Hb);
    cudaGetSymbolAddress((void**)&Sc,  g_Sc);
    cudaGetSymbolAddress((void**)&Wth, g_Wth);
    cudaGetSymbolAddress((void**)&cnt, g_cnt);

    cudaFuncSetAttribute(gcn_persistent,
                         cudaFuncAttributeMaxDynamicSharedMemorySize, SMEM_BYTES);

    cudaMemsetAsync(cnt, 0, 6 * 32 * 4 * sizeof(int));
    preproc<<<16384 + 768, 256>>>(X, adj, W0, W1, W2, Xh, Jh, Wth);
    gcn_persistent<<<NCTA, 256, SMEM_BYTES>>>(Xh, Jh, Wth, Sa, Ha, Sb, Hb, Sc,
                                              b0, b1, b2, out, cnt);
}